// round 7
// baseline (speedup 1.0000x reference)
#include <cuda_runtime.h>
#include <cstdint>

#define H     1024
#define V     32000
#define DEPTH 10
#define KDIM  1024

// ---------------- scratch (no runtime allocation allowed) ----------------
__device__ float g_h0[1024 * H];          // 4 MB  ping
__device__ float g_h1[1024 * H];          // 4 MB  pong
__device__ float g_gh[512 * 6 * H];       // 12.6 MB gate pre-activations

// ---------------- tf32 GEMM:  C[M,Ntot] = A[M,K] @ B^T + bias ------------
// B is given as rows of length K (K-major), i.e. C[m,n] = dot(A[m,:], B[n,:]).
// Columns n < nsplit use (B0, bias0); columns >= nsplit use (B1, bias1).
#define BM 128
#define BN 128
#define BK 32
#define PAD 4

__device__ __forceinline__ float cvt_tf32(float x) {
    uint32_t b;
    asm("cvt.rna.tf32.f32 %0, %1;" : "=r"(b) : "f"(x));
    return __uint_as_float(b);
}

__device__ __forceinline__ void mma_16x8x8(float c[4], const uint32_t a[4], const uint32_t b[2]) {
    asm volatile(
        "mma.sync.aligned.m16n8k8.row.col.f32.tf32.tf32.f32 "
        "{%0,%1,%2,%3}, {%4,%5,%6,%7}, {%8,%9}, {%0,%1,%2,%3};\n"
        : "+f"(c[0]), "+f"(c[1]), "+f"(c[2]), "+f"(c[3])
        : "r"(a[0]), "r"(a[1]), "r"(a[2]), "r"(a[3]), "r"(b[0]), "r"(b[1]));
}

__global__ void __launch_bounds__(256, 1)
gemm_tf32(const float* __restrict__ A, int M,
          const float* __restrict__ B0, const float* __restrict__ B1, int nsplit,
          const float* __restrict__ bias0, const float* __restrict__ bias1,
          float* __restrict__ C, int Ntot)
{
    __shared__ float sA[BM][BK + PAD];   // 18 KB
    __shared__ float sB[BN][BK + PAD];   // 18 KB

    const int tid  = threadIdx.x;
    const int lane = tid & 31;
    const int warp = tid >> 5;
    const int wm = (warp >> 2) * 64;     // warp m-origin within block tile
    const int wn = (warp & 3) * 32;      // warp n-origin within block tile
    const int bm = blockIdx.y * BM;
    const int bn = blockIdx.x * BN;

    const int lr = tid >> 3;             // 0..31 : tile row (step 32)
    const int lc = (tid & 7) * 4;        // 0..28 : k offset (float4)

    float acc[4][4][4];
    #pragma unroll
    for (int i = 0; i < 4; i++)
        #pragma unroll
        for (int j = 0; j < 4; j++)
            #pragma unroll
            for (int k = 0; k < 4; k++) acc[i][j][k] = 0.f;

    // per-thread source rows
    const float* Arow[4];
    const float* Brow[4];
    bool aval[4];
    #pragma unroll
    for (int i = 0; i < 4; i++) {
        int m = bm + lr + 32 * i;
        aval[i] = (m < M);
        Arow[i] = A + (size_t)(aval[i] ? m : 0) * KDIM;
        int n = bn + lr + 32 * i;
        Brow[i] = (n < nsplit) ? (B0 + (size_t)n * KDIM)
                               : (B1 + (size_t)(n - nsplit) * KDIM);
    }

    float4 pa[4], pb[4];
    #pragma unroll
    for (int i = 0; i < 4; i++) {
        pa[i] = aval[i] ? *(const float4*)(Arow[i] + lc) : make_float4(0.f, 0.f, 0.f, 0.f);
        pb[i] = *(const float4*)(Brow[i] + lc);
    }

    const int NK = KDIM / BK;            // 32 k-tiles
    for (int kt = 0; kt < NK; kt++) {
        // commit prefetched tile to smem with tf32 rounding
        #pragma unroll
        for (int i = 0; i < 4; i++) {
            float4 va = pa[i];
            va.x = cvt_tf32(va.x); va.y = cvt_tf32(va.y);
            va.z = cvt_tf32(va.z); va.w = cvt_tf32(va.w);
            *(float4*)&sA[lr + 32 * i][lc] = va;
            float4 vb = pb[i];
            vb.x = cvt_tf32(vb.x); vb.y = cvt_tf32(vb.y);
            vb.z = cvt_tf32(vb.z); vb.w = cvt_tf32(vb.w);
            *(float4*)&sB[lr + 32 * i][lc] = vb;
        }
        __syncthreads();

        if (kt + 1 < NK) {
            const int k0 = (kt + 1) * BK;
            #pragma unroll
            for (int i = 0; i < 4; i++) {
                pa[i] = aval[i] ? *(const float4*)(Arow[i] + k0 + lc)
                                : make_float4(0.f, 0.f, 0.f, 0.f);
                pb[i] = *(const float4*)(Brow[i] + k0 + lc);
            }
        }

        #pragma unroll
        for (int kk = 0; kk < 4; kk++) {
            const int k = kk * 8;
            uint32_t af[4][4];
            #pragma unroll
            for (int mf = 0; mf < 4; mf++) {
                int r0 = wm + mf * 16 + (lane >> 2);
                int c0 = k + (lane & 3);
                af[mf][0] = __float_as_uint(sA[r0][c0]);
                af[mf][1] = __float_as_uint(sA[r0 + 8][c0]);
                af[mf][2] = __float_as_uint(sA[r0][c0 + 4]);
                af[mf][3] = __float_as_uint(sA[r0 + 8][c0 + 4]);
            }
            uint32_t bf[4][2];
            #pragma unroll
            for (int nf = 0; nf < 4; nf++) {
                int n0 = wn + nf * 8 + (lane >> 2);
                int kr = k + (lane & 3);
                bf[nf][0] = __float_as_uint(sB[n0][kr]);
                bf[nf][1] = __float_as_uint(sB[n0][kr + 4]);
            }
            #pragma unroll
            for (int mf = 0; mf < 4; mf++)
                #pragma unroll
                for (int nf = 0; nf < 4; nf++)
                    mma_16x8x8(acc[mf][nf], af[mf], bf[nf]);
        }
        __syncthreads();
    }

    // epilogue: + bias, store
    #pragma unroll
    for (int nf = 0; nf < 4; nf++) {
        int c0 = bn + wn + nf * 8 + (lane & 3) * 2;       // 8-aligned frag, never straddles nsplit
        const float* bp = (c0 < nsplit) ? bias0 : bias1;
        int cb = (c0 < nsplit) ? c0 : c0 - nsplit;
        float bv0 = bp[cb], bv1 = bp[cb + 1];
        #pragma unroll
        for (int mf = 0; mf < 4; mf++) {
            int r0 = bm + wm + mf * 16 + (lane >> 2);
            if (r0 < M) {
                C[(size_t)r0 * Ntot + c0]     = acc[mf][nf][0] + bv0;
                C[(size_t)r0 * Ntot + c0 + 1] = acc[mf][nf][1] + bv1;
            }
            if (r0 + 8 < M) {
                C[(size_t)(r0 + 8) * Ntot + c0]     = acc[mf][nf][2] + bv0;
                C[(size_t)(r0 + 8) * Ntot + c0 + 1] = acc[mf][nf][3] + bv1;
            }
        }
    }
}

// ---------------- GRU gate fusion + interleave ---------------------------
__device__ __forceinline__ float sigmoidf_(float x) { return 1.f / (1.f + expf(-x)); }

__global__ void gru_gates(const float* __restrict__ hcur,
                          const float* __restrict__ bih_l,
                          const float* __restrict__ bih_r,
                          float* __restrict__ hnext, int M)
{
    int idx = blockIdx.x * blockDim.x + threadIdx.x;
    if (idx >= M * H) return;
    int n = idx >> 10;
    int j = idx & (H - 1);
    float h = hcur[idx];
    const float* gh = g_gh + (size_t)n * (6 * H);   // bhh already added by GEMM

    {   // left child -> row 2n
        float r  = sigmoidf_(bih_l[j]         + gh[j]);
        float z  = sigmoidf_(bih_l[H + j]     + gh[H + j]);
        float nn = tanhf   (bih_l[2 * H + j]  + r * gh[2 * H + j]);
        hnext[(size_t)(2 * n) * H + j] = (1.f - z) * nn + z * h;
    }
    {   // right child -> row 2n+1
        const float* ghr = gh + 3 * H;
        float r  = sigmoidf_(bih_r[j]         + ghr[j]);
        float z  = sigmoidf_(bih_r[H + j]     + ghr[H + j]);
        float nn = tanhf   (bih_r[2 * H + j]  + r * ghr[2 * H + j]);
        hnext[(size_t)(2 * n + 1) * H + j] = (1.f - z) * nn + z * h;
    }
}

// ---------------- row-wise log_softmax (in place) ------------------------
__global__ void __launch_bounds__(256) log_softmax_rows(float* __restrict__ out)
{
    const int row = blockIdx.x;
    float* x = out + (size_t)row * V;
    __shared__ float redm[8];
    __shared__ float reds[8];
    const int tid = threadIdx.x, lane = tid & 31, warp = tid >> 5;

    float m = -1e30f;
    for (int i = tid; i < V; i += 256) m = fmaxf(m, x[i]);
    #pragma unroll
    for (int o = 16; o; o >>= 1) m = fmaxf(m, __shfl_xor_sync(0xffffffffu, m, o));
    if (lane == 0) redm[warp] = m;
    __syncthreads();
    if (warp == 0) {
        m = (lane < 8) ? redm[lane] : -1e30f;
        #pragma unroll
        for (int o = 4; o; o >>= 1) m = fmaxf(m, __shfl_xor_sync(0xffffffffu, m, o));
        if (lane == 0) redm[0] = m;
    }
    __syncthreads();
    m = redm[0];

    float s = 0.f;
    for (int i = tid; i < V; i += 256) s += expf(x[i] - m);
    #pragma unroll
    for (int o = 16; o; o >>= 1) s += __shfl_xor_sync(0xffffffffu, s, o);
    if (lane == 0) reds[warp] = s;
    __syncthreads();
    if (warp == 0) {
        s = (lane < 8) ? reds[lane] : 0.f;
        #pragma unroll
        for (int o = 4; o; o >>= 1) s += __shfl_xor_sync(0xffffffffu, s, o);
        if (lane == 0) reds[0] = s;
    }
    __syncthreads();
    const float lse = m + logf(reds[0]);

    for (int i = tid; i < V; i += 256) x[i] = x[i] - lse;
}

// ---------------- launch ----------------------------------------------------
extern "C" void kernel_launch(void* const* d_in, const int* in_sizes, int n_in,
                              void* d_out, int out_size)
{
    const float* hidden = (const float*)d_in[0];
    const float* Whh_l  = (const float*)d_in[1];
    const float* bih_l  = (const float*)d_in[2];
    const float* bhh_l  = (const float*)d_in[3];
    const float* Whh_r  = (const float*)d_in[4];
    const float* bih_r  = (const float*)d_in[5];
    const float* bhh_r  = (const float*)d_in[6];
    const float* Wout   = (const float*)d_in[7];
    const float* bout   = (const float*)d_in[8];
    float* out = (float*)d_out;

    float *h0, *h1, *gh;
    cudaGetSymbolAddress((void**)&h0, g_h0);
    cudaGetSymbolAddress((void**)&h1, g_h1);
    cudaGetSymbolAddress((void**)&gh, g_gh);

    // root hidden state -> ping buffer
    cudaMemcpyAsync(h0, hidden, H * sizeof(float), cudaMemcpyDeviceToDevice);

    float* cur = h0;
    float* nxt = h1;
    for (int d = 0; d < DEPTH; d++) {
        const int M = 1 << d;
        dim3 grid(6 * H / BN, (M + BM - 1) / BM);            // (48, ceil(M/128))
        gemm_tf32<<<grid, 256>>>(cur, M, Whh_l, Whh_r, 3 * H,
                                 bhh_l, bhh_r, gh, 6 * H);
        const int tot = M * H;
        gru_gates<<<(tot + 255) / 256, 256>>>(cur, bih_l, bih_r, nxt, M);
        float* t = cur; cur = nxt; nxt = t;
    }

    // logits = h @ Wout^T + bout   (written directly into d_out)
    dim3 gridf(V / BN, 1024 / BM);                           // (250, 8)
    gemm_tf32<<<gridf, 256>>>(cur, 1024, Wout, Wout, V,
                              bout, bout, out, V);

    log_softmax_rows<<<1024, 256>>>(out);
}